// round 3
// baseline (speedup 1.0000x reference)
#include <cuda_runtime.h>
#include <math.h>

#define BB 16
#define HH 512
#define WW 512
#define HW (HH*WW)
#define NPIX (BB*HW)
#define WORDS_ROW 16           // 512/32
#define WORDS_IMG (HH*WORDS_ROW)

// morph tiling
#define TR 64                  // center rows per block
#define HALO 9
#define SR (TR + 2*HALO)       // 82 rows in smem
#define SW (SR*WORDS_ROW)      // 1312 words

// ---------------- scratch (device globals: alloc-free rule) ----------------
static __device__ float    g_gray[NPIX];
static __device__ int      g_hist[BB*32];
static __device__ float    g_thr[BB];
static __device__ unsigned g_nucbits[BB*WORDS_IMG];
static __device__ unsigned g_cellbits[BB*WORDS_IMG];
static __device__ unsigned g_bndbits[BB*WORDS_IMG];
static __device__ float    g_par[13];          // sp(cal_a)[4], cal_b[4], alpha[4], tau
static __device__ float    g_part[BB*256*2];   // per-tile (max, sumexp)
static __device__ float    g_red[BB*2];        // per-batch (max, sumexp)

__device__ __forceinline__ float softplusf(float v){
    return fmaxf(v, 0.0f) + log1pf(expf(-fabsf(v)));
}

// ---------------- gray + histogram ----------------
__global__ void k_zero_hist(){
    int i = blockIdx.x*blockDim.x + threadIdx.x;
    if (i < BB*32) g_hist[i] = 0;
}

__global__ void k_gray_hist(const float* __restrict__ img){
    __shared__ int sh[32];
    int t = threadIdx.x;
    if (t < 32) sh[t] = 0;
    __syncthreads();
    int b = blockIdx.y;
    int p = blockIdx.x*blockDim.x + t;
    const float* im = img + (size_t)b*3*HW;
    float r  = im[p];
    float gg = im[HW + p];
    float bl = im[2*HW + p];
    float gray = 0.5f*(0.299f*r + 0.587f*gg + 0.114f*bl + 1.0f);
    gray = fminf(fmaxf(gray, 0.0f), 1.0f);
    g_gray[(size_t)b*HW + p] = gray;
    int idx = (int)(gray*32.0f);
    idx = idx < 0 ? 0 : (idx > 31 ? 31 : idx);
    atomicAdd(&sh[idx], 1);
    __syncthreads();
    if (t < 32) atomicAdd(&g_hist[b*32 + t], sh[t]);
}

// ---------------- Otsu + scalar params ----------------
__global__ void k_otsu_params(const float* __restrict__ cal_a, const float* __restrict__ cal_b,
                              const float* __restrict__ alpha_logits, const float* __restrict__ tau_p){
    int b = blockIdx.x;
    if (threadIdx.x != 0) return;
    float omega[32], mu[32];
    float denom = (float)HW + 1e-6f;
    float o = 0.0f, m = 0.0f;
    for (int k = 0; k < 32; k++){
        float pk = (float)g_hist[b*32 + k] / denom;
        float xk = (float)k / 31.0f;
        o += pk; m += pk*xk;
        omega[k] = o; mu[k] = m;
    }
    float mu_t = mu[31];
    float best = -1e30f; int kb = 0;
    for (int k = 0; k < 32; k++){
        float num = mu_t*omega[k] - mu[k];
        float s   = num*num / (omega[k]*(1.0f - omega[k]) + 1e-8f);
        if (s > best){ best = s; kb = k; }
    }
    g_thr[b] = (float)kb / 32.0f;
    if (b == 0){
        float al[4]; float mx = -1e30f;
        for (int c = 0; c < 4; c++){ al[c] = alpha_logits[c]; mx = fmaxf(mx, al[c]); }
        float s = 0.0f;
        for (int c = 0; c < 4; c++){ al[c] = expf(al[c] - mx); s += al[c]; }
        for (int c = 0; c < 4; c++){
            g_par[c]     = softplusf(cal_a[c]);
            g_par[4 + c] = cal_b[c];
            g_par[8 + c] = al[c]/s;
        }
        g_par[12] = 0.2f + softplusf(tau_p[0]);
    }
}

// ---------------- bit-packed morphology: tiled, 128 blocks ----------------
__device__ __forceinline__ unsigned h_ero(const unsigned* S, int r, int k){
    unsigned w = S[r*WORDS_ROW + k];
    unsigned p = (k > 0)             ? S[r*WORDS_ROW + k - 1] : 0u;
    unsigned n = (k < WORDS_ROW - 1) ? S[r*WORDS_ROW + k + 1] : 0u;
    unsigned L = (w << 1) | ((k > 0)             ? (p >> 31) : 1u);
    unsigned R = (w >> 1) | ((k < WORDS_ROW - 1) ? (n << 31) : 0x80000000u);
    return L & w & R;
}
__device__ __forceinline__ unsigned h_dil(const unsigned* S, int r, int k){
    unsigned w = S[r*WORDS_ROW + k];
    unsigned p = (k > 0)             ? S[r*WORDS_ROW + k - 1] : 0u;
    unsigned n = (k < WORDS_ROW - 1) ? S[r*WORDS_ROW + k + 1] : 0u;
    unsigned L = (w << 1) | (p >> 31);
    unsigned R = (w >> 1) | (n << 31);
    return L | w | R;
}
// vertical combine with global-boundary awareness; r guarded to tile bounds
__device__ __forceinline__ unsigned erode3T(const unsigned* S, int r, int k, int gy){
    unsigned v = h_ero(S, r, k);
    if (gy > 0     && r > 0)      v &= h_ero(S, r-1, k);
    if (gy < HH-1  && r < SR-1)   v &= h_ero(S, r+1, k);
    return v;
}
__device__ __forceinline__ unsigned dilate3T(const unsigned* S, int r, int k, int gy){
    unsigned v = h_dil(S, r, k);
    if (gy > 0     && r > 0)      v |= h_dil(S, r-1, k);
    if (gy < HH-1  && r < SR-1)   v |= h_dil(S, r+1, k);
    return v;
}

#define MORPH_STEP(FN)                                              \
    {                                                               \
        unsigned nv[3];                                             \
        _Pragma("unroll")                                           \
        for (int s = 0; s < 3; s++){                                \
            int idx = tid + s*512;                                  \
            if (idx < SW){                                          \
                int r = idx >> 4, k = idx & 15;                     \
                nv[s] = FN(S, r, k, ty0 - HALO + r);                \
            }                                                       \
        }                                                           \
        __syncthreads();                                            \
        _Pragma("unroll")                                           \
        for (int s = 0; s < 3; s++){                                \
            int idx = tid + s*512;                                  \
            if (idx < SW) S[idx] = nv[s];                           \
        }                                                           \
        __syncthreads();                                            \
    }

__global__ void __launch_bounds__(512) k_morph(){
    __shared__ unsigned S[SW];
    int b   = blockIdx.y;
    int ty0 = blockIdx.x*TR;      // first center row (global)
    int tid = threadIdx.x;
    float thr = g_thr[b];
    const float* g = g_gray + (size_t)b*HW;

    // threshold -> bits (rows ty0-9 .. ty0+72; zero outside image, never consumed)
    #pragma unroll
    for (int s = 0; s < 3; s++){
        int idx = tid + s*512;
        if (idx < SW){
            int r = idx >> 4, k = idx & 15;
            int gy = ty0 - HALO + r;
            unsigned w = 0;
            if (gy >= 0 && gy < HH){
                const float* row = g + gy*WW + k*32;
                #pragma unroll
                for (int j = 0; j < 32; j++)
                    w |= (row[j] <= thr) ? (1u << j) : 0u;
            }
            S[idx] = w;
        }
    }
    __syncthreads();

    MORPH_STEP(erode3T)    // min3
    MORPH_STEP(dilate3T)   // max3
    MORPH_STEP(dilate3T)   // max3
    MORPH_STEP(erode3T)    // min3 -> S = nuc, valid rows [4, 77]

    // nuc + bnd output for center rows; rowmax11 into registers for all rows
    #pragma unroll
    for (int s = 0; s < 2; s++){
        int idx = tid + s*512;     // center rows: 64*16 = 1024 words
        int r = (idx >> 4) + HALO, k = idx & 15;
        int gy = ty0 - HALO + r;
        unsigned nu = S[r*WORDS_ROW + k];
        unsigned er = erode3T(S, r, k, gy);
        g_nucbits[b*WORDS_IMG + gy*WORDS_ROW + k] = nu;
        g_bndbits[b*WORDS_IMG + gy*WORDS_ROW + k] = nu & ~er;
    }
    // rowmax11 over S (valid wherever nuc valid)
    {
        unsigned nv[3];
        #pragma unroll
        for (int s = 0; s < 3; s++){
            int idx = tid + s*512;
            if (idx < SW){
                int r = idx >> 4, k = idx & 15;
                unsigned w = S[r*WORDS_ROW + k];
                unsigned p = (k > 0)             ? S[r*WORDS_ROW + k - 1] : 0u;
                unsigned n = (k < WORDS_ROW - 1) ? S[r*WORDS_ROW + k + 1] : 0u;
                unsigned long long lo = ((unsigned long long)w << 32) | p;
                unsigned long long hi = ((unsigned long long)n << 32) | w;
                unsigned v = w;
                #pragma unroll
                for (int sh = 1; sh <= 5; sh++){
                    v |= (unsigned)(lo >> (32 - sh));
                    v |= (unsigned)(hi >> sh);
                }
                nv[s] = v;
            }
        }
        __syncthreads();
        #pragma unroll
        for (int s = 0; s < 3; s++){
            int idx = tid + s*512;
            if (idx < SW) S[idx] = nv[s];
        }
        __syncthreads();
    }
    // colmax11 -> cell bits for center rows
    #pragma unroll
    for (int s = 0; s < 2; s++){
        int idx = tid + s*512;
        int r = (idx >> 4) + HALO, k = idx & 15;
        int gy = ty0 - HALO + r;
        int d0 = (gy - 5 < 0)    ? -gy          : -5;
        int d1 = (gy + 5 > HH-1) ? (HH-1 - gy)  :  5;
        unsigned v = 0;
        for (int d = d0; d <= d1; d++) v |= S[(r + d)*WORDS_ROW + k];
        g_cellbits[b*WORDS_IMG + gy*WORDS_ROW + k] = v;
    }
}

// ---------------- fused maps kernel ----------------
__device__ __forceinline__ unsigned winN(const unsigned* w3, int rel, int width){
    unsigned long long c = ((unsigned long long)w3[1] << 32) | (unsigned long long)w3[0];
    unsigned long long v = c >> rel;
    if (rel + width > 64) v |= ((unsigned long long)w3[2]) << (64 - rel);
    return (unsigned)v & ((1u << width) - 1u);
}
__device__ __forceinline__ unsigned bit1(const unsigned* w3, int pos){
    return (w3[pos >> 5] >> (pos & 31)) & 1u;
}

__global__ void __launch_bounds__(1024) k_fused(float* __restrict__ out){
    __shared__ float sg[42*43];
    __shared__ float ssn[40*40];
    __shared__ float scs[40*40];
    __shared__ float vs0[32*40], vs1[32*40], vs2[32*40], vs3[32*40];
    __shared__ unsigned nucw[40*3], cellw[40*3], bndw[40*3];

    int tx = threadIdx.x, ty = threadIdx.y;
    int tid = ty*32 + tx;
    int tx0 = blockIdx.x*32, ty0 = blockIdx.y*32;
    int b = blockIdx.z;
    const float* g = g_gray + (size_t)b*HW;

    for (int idx = tid; idx < 42*42; idx += 1024){
        int rr = idx/42, cc = idx%42;
        int gy = ty0 - 5 + rr, gx = tx0 - 5 + cc;
        float v = 0.0f;
        if (gy >= 0 && gy < HH && gx >= 0 && gx < WW) v = g[gy*WW + gx];
        sg[rr*43 + cc] = v;
    }
    {
        int kw0 = (tx0 >> 5) - 1;
        for (int idx = tid; idx < 120; idx += 1024){
            int r = idx/3, c = idx%3;
            int gy = ty0 - 4 + r;
            int kw = kw0 + c;
            unsigned nv = 0, cv = 0, bv = 0;
            if (gy >= 0 && gy < HH && kw >= 0 && kw < WORDS_ROW){
                int off = b*WORDS_IMG + gy*WORDS_ROW + kw;
                nv = g_nucbits[off]; cv = g_cellbits[off]; bv = g_bndbits[off];
            }
            nucw[idx] = nv; cellw[idx] = cv; bndw[idx] = bv;
        }
    }
    __syncthreads();

    for (int idx = tid; idx < 40*40; idx += 1024){
        int r = idx/40, c = idx%40;
        int gy = ty0 - 4 + r, gx = tx0 - 4 + c;
        float sn = 0.0f, cs = 0.0f;
        if (gy >= 0 && gy < HH && gx >= 0 && gx < WW){
            const float* p = sg + r*43 + c;
            float v00 = p[0],  v01 = p[1],  v02 = p[2];
            float v10 = p[43],              v12 = p[45];
            float v20 = p[86], v21 = p[87], v22 = p[88];
            float gxv = (v00 + 2.0f*v10 + v20) - (v02 + 2.0f*v12 + v22);
            float gyv = (v00 + 2.0f*v01 + v02) - (v20 + 2.0f*v21 + v22);
            float r2 = gxv*gxv + gyv*gyv;
            if (r2 > 0.0f){
                float rr = sqrtf(r2);
                sn = gyv/rr; cs = gxv/rr;
            } else { sn = 0.0f; cs = 1.0f; }
        }
        ssn[idx] = sn; scs[idx] = cs;
    }
    __syncthreads();

    for (int idx = tid; idx < 32*40; idx += 1024){
        int yi = idx/40, j = idx%40;
        float a = 0.0f, bq = 0.0f, cq = 0.0f, dq = 0.0f;
        #pragma unroll
        for (int k = 0; k < 9; k++){
            a  += ssn[(yi+k)*40 + j];
            bq += scs[(yi+k)*40 + j];
            float gv = sg[(yi+1+k)*43 + (j+1)];
            cq += gv;
            dq += gv*gv;
        }
        vs0[idx] = a; vs1[idx] = bq; vs2[idx] = cq; vs3[idx] = dq;
    }
    __syncthreads();

    int xi = tx, yi = ty;
    int gx = tx0 + xi, gy = ty0 + yi;
    float s_sn = 0.0f, s_cs = 0.0f, s_g = 0.0f, s_g2 = 0.0f;
    #pragma unroll
    for (int k = 0; k < 9; k++){
        int j = yi*40 + xi + k;
        s_sn += vs0[j]; s_cs += vs1[j]; s_g += vs2[j]; s_g2 += vs3[j];
    }
    int rows_in = (gy+4 > HH-1 ? HH-1 : gy+4) - (gy-4 < 0 ? 0 : gy-4) + 1;
    int cols_in = (gx+4 > WW-1 ? WW-1 : gx+4) - (gx-4 < 0 ? 0 : gx-4) + 1;
    float den = (float)(rows_in*cols_in) + 1e-6f;

    float ms = s_sn/den, mc = s_cs/den;
    float circ = 1.0f - sqrtf(ms*ms + mc*mc + 1e-6f);
    float g1 = s_g/den, g2v = s_g2/den;
    float ent = log1pf(fmaxf(g2v - g1*g1, 0.0f));

    int an = 0, csum = 0;
    #pragma unroll
    for (int k = 0; k < 9; k++){
        an   += __popc(winN(&nucw[(yi+k)*3],  xi + 28, 9));
        csum += __popc(winN(&cellw[(yi+k)*3], xi + 28, 9));
    }
    float A_n = (float)an;
    float A_c = fmaxf((float)(csum - an), 1.0f);
    float ncv = A_n / A_c;

    unsigned cbit = bit1(&nucw[(yi+4)*3], xi + 32);
    unsigned up   = bit1(&nucw[(yi+3)*3], xi + 32);
    unsigned dn   = bit1(&nucw[(yi+5)*3], xi + 32);
    unsigned lf   = bit1(&nucw[(yi+4)*3], xi + 31);
    unsigned rt   = bit1(&nucw[(yi+4)*3], xi + 33);
    float lap = fabsf((float)(up + dn + lf + rt) - 4.0f*(float)cbit);
    unsigned bc = bit1(&bndw[(yi+4)*3], xi + 32);
    int bs = 0;
    #pragma unroll
    for (int k = 0; k < 5; k++)
        bs += __popc(winN(&bndw[(yi+2+k)*3], xi + 30, 5));
    float rough = lap*(float)bc / ((float)bs + 1e-6f);

    size_t pix = (size_t)gy*WW + gx;
    float* z = out + (size_t)NPIX + (size_t)b*4*HW + pix;
    z[0]     = rough;
    z[HW]    = circ;
    z[2*HW]  = ncv;
    z[3*HW]  = ent;
    out[5*(size_t)NPIX + (size_t)b*HW + pix] = (float)cbit;

    float z0s = log1pf(fmaxf(rough, 0.0f));
    float z1s = fminf(fmaxf(circ, 0.0f), 1.0f);
    float z2s = log1pf(fmaxf(ncv, 0.0f));
    float z3s = fminf(fmaxf(ent, 0.0f), 3.4657359f);
    float E = g_par[8 ]*(g_par[0]*z0s + g_par[4])
            + g_par[9 ]*(g_par[1]*z1s + g_par[5])
            + g_par[10]*(g_par[2]*z2s + g_par[6])
            + g_par[11]*(g_par[3]*z3s + g_par[7]);
    out[6*(size_t)NPIX + (size_t)b*HW + pix] = E;

    float invtau = 1.0f / g_par[12];
    float zz = -E*invtau;
    float* red = ssn;
    red[tid] = zz;
    __syncthreads();
    for (int s = 512; s > 0; s >>= 1){
        if (tid < s) red[tid] = fmaxf(red[tid], red[tid + s]);
        __syncthreads();
    }
    float m = red[0];
    __syncthreads();
    red[tid] = expf(zz - m);
    __syncthreads();
    for (int s = 512; s > 0; s >>= 1){
        if (tid < s) red[tid] += red[tid + s];
        __syncthreads();
    }
    if (tid == 0){
        int tile = blockIdx.y*16 + blockIdx.x;
        g_part[(b*256 + tile)*2    ] = m;
        g_part[(b*256 + tile)*2 + 1] = red[0];
    }
}

// ---------------- combine softmax partials ----------------
__global__ void k_combine(){
    __shared__ float sm[256], ss[256];
    int b = blockIdx.x, t = threadIdx.x;
    float m = g_part[(b*256 + t)*2];
    float s = g_part[(b*256 + t)*2 + 1];
    sm[t] = m;
    __syncthreads();
    for (int st = 128; st > 0; st >>= 1){
        if (t < st) sm[t] = fmaxf(sm[t], sm[t + st]);
        __syncthreads();
    }
    float M = sm[0];
    __syncthreads();
    ss[t] = s*expf(m - M);
    __syncthreads();
    for (int st = 128; st > 0; st >>= 1){
        if (t < st) ss[t] += ss[t + st];
        __syncthreads();
    }
    if (t == 0){ g_red[b*2] = M; g_red[b*2 + 1] = ss[0]; }
}

// ---------------- final A ----------------
__global__ void k_A(float* __restrict__ out){
    int b = blockIdx.y;
    int p = blockIdx.x*blockDim.x + threadIdx.x;
    float invtau = 1.0f / g_par[12];
    float M = g_red[b*2];
    float S = g_red[b*2 + 1];
    float E = out[6*(size_t)NPIX + (size_t)b*HW + p];
    out[(size_t)b*HW + p] = expf(-E*invtau - M) / S;
}

// ---------------- launch ----------------
extern "C" void kernel_launch(void* const* d_in, const int* in_sizes, int n_in,
                              void* d_out, int out_size){
    const float* img    = (const float*)d_in[0];
    const float* cal_a  = (const float*)d_in[1];
    const float* cal_b  = (const float*)d_in[2];
    const float* alpha  = (const float*)d_in[3];
    const float* tau_p  = (const float*)d_in[4];
    float* out = (float*)d_out;
    (void)in_sizes; (void)n_in; (void)out_size;

    dim3 blk1(256, 1, 1);
    dim3 grd1(HW/256, BB, 1);

    k_zero_hist<<<2, 256>>>();
    k_gray_hist<<<grd1, blk1>>>(img);
    k_otsu_params<<<BB, 32>>>(cal_a, cal_b, alpha, tau_p);
    k_morph<<<dim3(HH/TR, BB, 1), 512>>>();
    k_fused<<<dim3(16, 16, BB), dim3(32, 32, 1)>>>(out);
    k_combine<<<BB, 256>>>();
    k_A<<<grd1, blk1>>>(out);
}

// round 4
// speedup vs baseline: 1.5449x; 1.5449x over previous
#include <cuda_runtime.h>
#include <math.h>

#define BB 16
#define HH 512
#define WW 512
#define HW (HH*WW)
#define NPIX (BB*HW)
#define WORDS_ROW 16           // 512/32
#define WORDS_IMG (HH*WORDS_ROW)

// morph tiling
#define TR 32                  // center rows per block
#define HALO 9
#define SR (TR + 2*HALO)       // 50 rows in smem
#define SW (SR*WORDS_ROW)      // 800 words
#define MT 256                 // morph threads

// ---------------- scratch (device globals: alloc-free rule) ----------------
static __device__ float    g_gray[NPIX];
static __device__ int      g_hist[BB*32];
static __device__ float    g_thr[BB];
static __device__ unsigned g_nucbits[BB*WORDS_IMG];
static __device__ unsigned g_cellbits[BB*WORDS_IMG];
static __device__ unsigned g_bndbits[BB*WORDS_IMG];
static __device__ float    g_par[13];          // sp(cal_a)[4], cal_b[4], alpha[4], tau
static __device__ float    g_part[BB*256*2];   // per-tile (max, sumexp)
static __device__ float    g_red[BB*2];        // per-batch (max, sumexp)

__device__ __forceinline__ float softplusf(float v){
    return fmaxf(v, 0.0f) + log1pf(expf(-fabsf(v)));
}

// ---------------- gray + histogram ----------------
__global__ void k_zero_hist(){
    int i = blockIdx.x*blockDim.x + threadIdx.x;
    if (i < BB*32) g_hist[i] = 0;
}

__global__ void k_gray_hist(const float* __restrict__ img){
    __shared__ int sh[32];
    int t = threadIdx.x;
    if (t < 32) sh[t] = 0;
    __syncthreads();
    int b = blockIdx.y;
    int p = blockIdx.x*blockDim.x + t;
    const float* im = img + (size_t)b*3*HW;
    float r  = __ldcs(im + p);
    float gg = __ldcs(im + HW + p);
    float bl = __ldcs(im + 2*HW + p);
    float gray = 0.5f*(0.299f*r + 0.587f*gg + 0.114f*bl + 1.0f);
    gray = fminf(fmaxf(gray, 0.0f), 1.0f);
    g_gray[(size_t)b*HW + p] = gray;
    int idx = (int)(gray*32.0f);
    idx = idx < 0 ? 0 : (idx > 31 ? 31 : idx);
    atomicAdd(&sh[idx], 1);
    __syncthreads();
    if (t < 32) atomicAdd(&g_hist[b*32 + t], sh[t]);
}

// ---------------- Otsu + scalar params ----------------
__global__ void k_otsu_params(const float* __restrict__ cal_a, const float* __restrict__ cal_b,
                              const float* __restrict__ alpha_logits, const float* __restrict__ tau_p){
    int b = blockIdx.x;
    if (threadIdx.x != 0) return;
    float omega[32], mu[32];
    float denom = (float)HW + 1e-6f;
    float o = 0.0f, m = 0.0f;
    for (int k = 0; k < 32; k++){
        float pk = (float)g_hist[b*32 + k] / denom;
        float xk = (float)k / 31.0f;
        o += pk; m += pk*xk;
        omega[k] = o; mu[k] = m;
    }
    float mu_t = mu[31];
    float best = -1e30f; int kb = 0;
    for (int k = 0; k < 32; k++){
        float num = mu_t*omega[k] - mu[k];
        float s   = num*num / (omega[k]*(1.0f - omega[k]) + 1e-8f);
        if (s > best){ best = s; kb = k; }
    }
    g_thr[b] = (float)kb / 32.0f;
    if (b == 0){
        float al[4]; float mx = -1e30f;
        for (int c = 0; c < 4; c++){ al[c] = alpha_logits[c]; mx = fmaxf(mx, al[c]); }
        float s = 0.0f;
        for (int c = 0; c < 4; c++){ al[c] = expf(al[c] - mx); s += al[c]; }
        for (int c = 0; c < 4; c++){
            g_par[c]     = softplusf(cal_a[c]);
            g_par[4 + c] = cal_b[c];
            g_par[8 + c] = al[c]/s;
        }
        g_par[12] = 0.2f + softplusf(tau_p[0]);
    }
}

// ---------------- bit-packed morphology: tiled, 256 blocks ----------------
__device__ __forceinline__ unsigned h_ero(const unsigned* S, int r, int k){
    unsigned w = S[r*WORDS_ROW + k];
    unsigned p = (k > 0)             ? S[r*WORDS_ROW + k - 1] : 0u;
    unsigned n = (k < WORDS_ROW - 1) ? S[r*WORDS_ROW + k + 1] : 0u;
    unsigned L = (w << 1) | ((k > 0)             ? (p >> 31) : 1u);
    unsigned R = (w >> 1) | ((k < WORDS_ROW - 1) ? (n << 31) : 0x80000000u);
    return L & w & R;
}
__device__ __forceinline__ unsigned h_dil(const unsigned* S, int r, int k){
    unsigned w = S[r*WORDS_ROW + k];
    unsigned p = (k > 0)             ? S[r*WORDS_ROW + k - 1] : 0u;
    unsigned n = (k < WORDS_ROW - 1) ? S[r*WORDS_ROW + k + 1] : 0u;
    unsigned L = (w << 1) | (p >> 31);
    unsigned R = (w >> 1) | (n << 31);
    return L | w | R;
}
__device__ __forceinline__ unsigned erode3T(const unsigned* S, int r, int k, int gy){
    unsigned v = h_ero(S, r, k);
    if (gy > 0     && r > 0)      v &= h_ero(S, r-1, k);
    if (gy < HH-1  && r < SR-1)   v &= h_ero(S, r+1, k);
    return v;
}
__device__ __forceinline__ unsigned dilate3T(const unsigned* S, int r, int k, int gy){
    unsigned v = h_dil(S, r, k);
    if (gy > 0     && r > 0)      v |= h_dil(S, r-1, k);
    if (gy < HH-1  && r < SR-1)   v |= h_dil(S, r+1, k);
    return v;
}

#define MORPH_STEP(FN)                                              \
    {                                                               \
        unsigned nv[4];                                             \
        _Pragma("unroll")                                           \
        for (int s = 0; s < 4; s++){                                \
            int idx = tid + s*MT;                                   \
            if (idx < SW){                                          \
                int r = idx >> 4, k = idx & 15;                     \
                nv[s] = FN(S, r, k, ty0 - HALO + r);                \
            }                                                       \
        }                                                           \
        __syncthreads();                                            \
        _Pragma("unroll")                                           \
        for (int s = 0; s < 4; s++){                                \
            int idx = tid + s*MT;                                   \
            if (idx < SW) S[idx] = nv[s];                           \
        }                                                           \
        __syncthreads();                                            \
    }

__global__ void __launch_bounds__(MT) k_morph(){
    __shared__ unsigned S[SW];
    int b   = blockIdx.y;
    int ty0 = blockIdx.x*TR;      // first center row (global)
    int tid = threadIdx.x;
    float thr = g_thr[b];
    const float* g = g_gray + (size_t)b*HW;

    // threshold -> bits
    #pragma unroll
    for (int s = 0; s < 4; s++){
        int idx = tid + s*MT;
        if (idx < SW){
            int r = idx >> 4, k = idx & 15;
            int gy = ty0 - HALO + r;
            unsigned w = 0;
            if (gy >= 0 && gy < HH){
                const float* row = g + gy*WW + k*32;
                #pragma unroll
                for (int j = 0; j < 32; j++)
                    w |= (row[j] <= thr) ? (1u << j) : 0u;
            }
            S[idx] = w;
        }
    }
    __syncthreads();

    MORPH_STEP(erode3T)    // min3
    MORPH_STEP(dilate3T)   // max3
    MORPH_STEP(dilate3T)   // max3
    MORPH_STEP(erode3T)    // min3 -> S = nuc, valid rows [4, SR-5]

    // nuc + bnd output for center rows
    #pragma unroll
    for (int s = 0; s < 2; s++){
        int idx = tid + s*MT;     // center rows: TR*16 = 512 words
        int r = (idx >> 4) + HALO, k = idx & 15;
        int gy = ty0 - HALO + r;
        unsigned nu = S[r*WORDS_ROW + k];
        unsigned er = erode3T(S, r, k, gy);
        g_nucbits[b*WORDS_IMG + gy*WORDS_ROW + k] = nu;
        g_bndbits[b*WORDS_IMG + gy*WORDS_ROW + k] = nu & ~er;
    }
    // rowmax11 over S
    {
        unsigned nv[4];
        #pragma unroll
        for (int s = 0; s < 4; s++){
            int idx = tid + s*MT;
            if (idx < SW){
                int r = idx >> 4, k = idx & 15;
                unsigned w = S[r*WORDS_ROW + k];
                unsigned p = (k > 0)             ? S[r*WORDS_ROW + k - 1] : 0u;
                unsigned n = (k < WORDS_ROW - 1) ? S[r*WORDS_ROW + k + 1] : 0u;
                unsigned long long lo = ((unsigned long long)w << 32) | p;
                unsigned long long hi = ((unsigned long long)n << 32) | w;
                unsigned v = w;
                #pragma unroll
                for (int sh = 1; sh <= 5; sh++){
                    v |= (unsigned)(lo >> (32 - sh));
                    v |= (unsigned)(hi >> sh);
                }
                nv[s] = v;
            }
        }
        __syncthreads();
        #pragma unroll
        for (int s = 0; s < 4; s++){
            int idx = tid + s*MT;
            if (idx < SW) S[idx] = nv[s];
        }
        __syncthreads();
    }
    // colmax11 -> cell bits for center rows
    #pragma unroll
    for (int s = 0; s < 2; s++){
        int idx = tid + s*MT;
        int r = (idx >> 4) + HALO, k = idx & 15;
        int gy = ty0 - HALO + r;
        int d0 = (gy - 5 < 0)    ? -gy          : -5;
        int d1 = (gy + 5 > HH-1) ? (HH-1 - gy)  :  5;
        unsigned v = 0;
        for (int d = d0; d <= d1; d++) v |= S[(r + d)*WORDS_ROW + k];
        g_cellbits[b*WORDS_IMG + gy*WORDS_ROW + k] = v;
    }
}

// ---------------- fused maps kernel ----------------
__device__ __forceinline__ unsigned winN(const unsigned* w3, int rel, int width){
    unsigned long long c = ((unsigned long long)w3[1] << 32) | (unsigned long long)w3[0];
    unsigned long long v = c >> rel;
    if (rel + width > 64) v |= ((unsigned long long)w3[2]) << (64 - rel);
    return (unsigned)v & ((1u << width) - 1u);
}
__device__ __forceinline__ unsigned bit1(const unsigned* w3, int pos){
    return (w3[pos >> 5] >> (pos & 31)) & 1u;
}

__global__ void __launch_bounds__(1024) k_fused(float* __restrict__ out){
    __shared__ float sg[42*43];
    __shared__ float ssn[40*40];
    __shared__ float scs[40*40];
    __shared__ float vs0[32*40], vs1[32*40], vs2[32*40], vs3[32*40];
    __shared__ unsigned nucw[40*3], cellw[40*3], bndw[40*3];

    int tx = threadIdx.x, ty = threadIdx.y;
    int tid = ty*32 + tx;
    int tx0 = blockIdx.x*32, ty0 = blockIdx.y*32;
    int b = blockIdx.z;
    const float* g = g_gray + (size_t)b*HW;

    for (int idx = tid; idx < 42*42; idx += 1024){
        int rr = idx/42, cc = idx%42;
        int gy = ty0 - 5 + rr, gx = tx0 - 5 + cc;
        float v = 0.0f;
        if (gy >= 0 && gy < HH && gx >= 0 && gx < WW) v = g[gy*WW + gx];
        sg[rr*43 + cc] = v;
    }
    {
        int kw0 = (tx0 >> 5) - 1;
        for (int idx = tid; idx < 120; idx += 1024){
            int r = idx/3, c = idx%3;
            int gy = ty0 - 4 + r;
            int kw = kw0 + c;
            unsigned nv = 0, cv = 0, bv = 0;
            if (gy >= 0 && gy < HH && kw >= 0 && kw < WORDS_ROW){
                int off = b*WORDS_IMG + gy*WORDS_ROW + kw;
                nv = g_nucbits[off]; cv = g_cellbits[off]; bv = g_bndbits[off];
            }
            nucw[idx] = nv; cellw[idx] = cv; bndw[idx] = bv;
        }
    }
    __syncthreads();

    for (int idx = tid; idx < 40*40; idx += 1024){
        int r = idx/40, c = idx%40;
        int gy = ty0 - 4 + r, gx = tx0 - 4 + c;
        float sn = 0.0f, cs = 0.0f;
        if (gy >= 0 && gy < HH && gx >= 0 && gx < WW){
            const float* p = sg + r*43 + c;
            float v00 = p[0],  v01 = p[1],  v02 = p[2];
            float v10 = p[43],              v12 = p[45];
            float v20 = p[86], v21 = p[87], v22 = p[88];
            float gxv = (v00 + 2.0f*v10 + v20) - (v02 + 2.0f*v12 + v22);
            float gyv = (v00 + 2.0f*v01 + v02) - (v20 + 2.0f*v21 + v22);
            float r2 = gxv*gxv + gyv*gyv;
            if (r2 > 0.0f){
                float rr = sqrtf(r2);
                sn = gyv/rr; cs = gxv/rr;
            } else { sn = 0.0f; cs = 1.0f; }
        }
        ssn[idx] = sn; scs[idx] = cs;
    }
    __syncthreads();

    for (int idx = tid; idx < 32*40; idx += 1024){
        int yi = idx/40, j = idx%40;
        float a = 0.0f, bq = 0.0f, cq = 0.0f, dq = 0.0f;
        #pragma unroll
        for (int k = 0; k < 9; k++){
            a  += ssn[(yi+k)*40 + j];
            bq += scs[(yi+k)*40 + j];
            float gv = sg[(yi+1+k)*43 + (j+1)];
            cq += gv;
            dq += gv*gv;
        }
        vs0[idx] = a; vs1[idx] = bq; vs2[idx] = cq; vs3[idx] = dq;
    }
    __syncthreads();

    int xi = tx, yi = ty;
    int gx = tx0 + xi, gy = ty0 + yi;
    float s_sn = 0.0f, s_cs = 0.0f, s_g = 0.0f, s_g2 = 0.0f;
    #pragma unroll
    for (int k = 0; k < 9; k++){
        int j = yi*40 + xi + k;
        s_sn += vs0[j]; s_cs += vs1[j]; s_g += vs2[j]; s_g2 += vs3[j];
    }
    int rows_in = (gy+4 > HH-1 ? HH-1 : gy+4) - (gy-4 < 0 ? 0 : gy-4) + 1;
    int cols_in = (gx+4 > WW-1 ? WW-1 : gx+4) - (gx-4 < 0 ? 0 : gx-4) + 1;
    float den = (float)(rows_in*cols_in) + 1e-6f;

    float ms = s_sn/den, mc = s_cs/den;
    float circ = 1.0f - sqrtf(ms*ms + mc*mc + 1e-6f);
    float g1 = s_g/den, g2v = s_g2/den;
    float ent = log1pf(fmaxf(g2v - g1*g1, 0.0f));

    int an = 0, csum = 0;
    #pragma unroll
    for (int k = 0; k < 9; k++){
        an   += __popc(winN(&nucw[(yi+k)*3],  xi + 28, 9));
        csum += __popc(winN(&cellw[(yi+k)*3], xi + 28, 9));
    }
    float A_n = (float)an;
    float A_c = fmaxf((float)(csum - an), 1.0f);
    float ncv = A_n / A_c;

    unsigned cbit = bit1(&nucw[(yi+4)*3], xi + 32);
    unsigned up   = bit1(&nucw[(yi+3)*3], xi + 32);
    unsigned dn   = bit1(&nucw[(yi+5)*3], xi + 32);
    unsigned lf   = bit1(&nucw[(yi+4)*3], xi + 31);
    unsigned rt   = bit1(&nucw[(yi+4)*3], xi + 33);
    float lap = fabsf((float)(up + dn + lf + rt) - 4.0f*(float)cbit);
    unsigned bc = bit1(&bndw[(yi+4)*3], xi + 32);
    int bs = 0;
    #pragma unroll
    for (int k = 0; k < 5; k++)
        bs += __popc(winN(&bndw[(yi+2+k)*3], xi + 30, 5));
    float rough = lap*(float)bc / ((float)bs + 1e-6f);

    size_t pix = (size_t)gy*WW + gx;
    float* z = out + (size_t)NPIX + (size_t)b*4*HW + pix;
    __stcs(z,        rough);
    __stcs(z + HW,   circ);
    __stcs(z + 2*HW, ncv);
    __stcs(z + 3*HW, ent);
    __stcs(out + 5*(size_t)NPIX + (size_t)b*HW + pix, (float)cbit);

    float z0s = log1pf(fmaxf(rough, 0.0f));
    float z1s = fminf(fmaxf(circ, 0.0f), 1.0f);
    float z2s = log1pf(fmaxf(ncv, 0.0f));
    float z3s = fminf(fmaxf(ent, 0.0f), 3.4657359f);
    float E = g_par[8 ]*(g_par[0]*z0s + g_par[4])
            + g_par[9 ]*(g_par[1]*z1s + g_par[5])
            + g_par[10]*(g_par[2]*z2s + g_par[6])
            + g_par[11]*(g_par[3]*z3s + g_par[7]);
    __stcs(out + 6*(size_t)NPIX + (size_t)b*HW + pix, E);

    float invtau = 1.0f / g_par[12];
    float zz = -E*invtau;
    float* red = ssn;
    red[tid] = zz;
    __syncthreads();
    for (int s = 512; s > 0; s >>= 1){
        if (tid < s) red[tid] = fmaxf(red[tid], red[tid + s]);
        __syncthreads();
    }
    float m = red[0];
    __syncthreads();
    red[tid] = expf(zz - m);
    __syncthreads();
    for (int s = 512; s > 0; s >>= 1){
        if (tid < s) red[tid] += red[tid + s];
        __syncthreads();
    }
    if (tid == 0){
        int tile = blockIdx.y*16 + blockIdx.x;
        g_part[(b*256 + tile)*2    ] = m;
        g_part[(b*256 + tile)*2 + 1] = red[0];
    }
}

// ---------------- combine softmax partials ----------------
__global__ void k_combine(){
    __shared__ float sm[256], ss[256];
    int b = blockIdx.x, t = threadIdx.x;
    float m = g_part[(b*256 + t)*2];
    float s = g_part[(b*256 + t)*2 + 1];
    sm[t] = m;
    __syncthreads();
    for (int st = 128; st > 0; st >>= 1){
        if (t < st) sm[t] = fmaxf(sm[t], sm[t + st]);
        __syncthreads();
    }
    float M = sm[0];
    __syncthreads();
    ss[t] = s*expf(m - M);
    __syncthreads();
    for (int st = 128; st > 0; st >>= 1){
        if (t < st) ss[t] += ss[t + st];
        __syncthreads();
    }
    if (t == 0){ g_red[b*2] = M; g_red[b*2 + 1] = ss[0]; }
}

// ---------------- final A ----------------
__global__ void k_A(float* __restrict__ out){
    int b = blockIdx.y;
    int p = blockIdx.x*blockDim.x + threadIdx.x;
    float invtau = 1.0f / g_par[12];
    float M = g_red[b*2];
    float S = g_red[b*2 + 1];
    float E = __ldcs(out + 6*(size_t)NPIX + (size_t)b*HW + p);
    __stcs(out + (size_t)b*HW + p, expf(-E*invtau - M) / S);
}

// ---------------- launch ----------------
extern "C" void kernel_launch(void* const* d_in, const int* in_sizes, int n_in,
                              void* d_out, int out_size){
    const float* img    = (const float*)d_in[0];
    const float* cal_a  = (const float*)d_in[1];
    const float* cal_b  = (const float*)d_in[2];
    const float* alpha  = (const float*)d_in[3];
    const float* tau_p  = (const float*)d_in[4];
    float* out = (float*)d_out;
    (void)in_sizes; (void)n_in; (void)out_size;

    dim3 blk1(256, 1, 1);
    dim3 grd1(HW/256, BB, 1);

    k_zero_hist<<<2, 256>>>();
    k_gray_hist<<<grd1, blk1>>>(img);
    k_otsu_params<<<BB, 32>>>(cal_a, cal_b, alpha, tau_p);
    k_morph<<<dim3(HH/TR, BB, 1), MT>>>();
    k_fused<<<dim3(16, 16, BB), dim3(32, 32, 1)>>>(out);
    k_combine<<<BB, 256>>>();
    k_A<<<grd1, blk1>>>(out);
}

// round 5
// speedup vs baseline: 1.9496x; 1.2619x over previous
#include <cuda_runtime.h>
#include <math.h>

#define BB 16
#define HH 512
#define WW 512
#define HW (HH*WW)
#define NPIX (BB*HW)
#define WORDS_ROW 16           // 512/32
#define WORDS_IMG (HH*WORDS_ROW)

// morph tiling
#define TR 16                  // center rows per block
#define HALO 9
#define SR (TR + 2*HALO)       // 34 rows in smem
#define SW (SR*WORDS_ROW)      // 544 words
#define MT 256                 // morph threads

// ---------------- scratch (device globals: alloc-free rule) ----------------
static __device__ float    g_gray[NPIX];
static __device__ int      g_hist[BB*32];
static __device__ float    g_thr[BB];
static __device__ unsigned g_nucbits[BB*WORDS_IMG];
static __device__ unsigned g_cellbits[BB*WORDS_IMG];
static __device__ unsigned g_bndbits[BB*WORDS_IMG];
static __device__ float    g_par[13];          // sp(cal_a)[4], cal_b[4], alpha[4], tau
static __device__ float    g_part[BB*256*2];   // per-tile (max, sumexp)
static __device__ float    g_red[BB*2];        // per-batch (max, sumexp)

__device__ __forceinline__ float softplusf(float v){
    return fmaxf(v, 0.0f) + log1pf(expf(-fabsf(v)));
}

// ---------------- gray + histogram (float4: 4 px/thread) ----------------
__global__ void k_zero_hist(){
    int i = blockIdx.x*blockDim.x + threadIdx.x;
    if (i < BB*32) g_hist[i] = 0;
}

__global__ void k_gray_hist(const float* __restrict__ img){
    __shared__ int sh[32];
    int t = threadIdx.x;
    if (t < 32) sh[t] = 0;
    __syncthreads();
    int b = blockIdx.y;
    int p4 = blockIdx.x*blockDim.x + t;         // float4 index
    const float4* imr = (const float4*)(img + (size_t)b*3*HW);
    const float4* img_ = imr + (HW/4);
    const float4* imb = imr + 2*(HW/4);
    float4 r4 = __ldcs(imr + p4);
    float4 g4 = __ldcs(img_ + p4);
    float4 b4 = __ldcs(imb + p4);
    float gr[4];
    gr[0] = 0.5f*(0.299f*r4.x + 0.587f*g4.x + 0.114f*b4.x + 1.0f);
    gr[1] = 0.5f*(0.299f*r4.y + 0.587f*g4.y + 0.114f*b4.y + 1.0f);
    gr[2] = 0.5f*(0.299f*r4.z + 0.587f*g4.z + 0.114f*b4.z + 1.0f);
    gr[3] = 0.5f*(0.299f*r4.w + 0.587f*g4.w + 0.114f*b4.w + 1.0f);
    float4 o;
    #pragma unroll
    for (int j = 0; j < 4; j++){
        gr[j] = fminf(fmaxf(gr[j], 0.0f), 1.0f);
        int idx = (int)(gr[j]*32.0f);
        idx = idx < 0 ? 0 : (idx > 31 ? 31 : idx);
        atomicAdd(&sh[idx], 1);
    }
    o.x = gr[0]; o.y = gr[1]; o.z = gr[2]; o.w = gr[3];
    ((float4*)(g_gray + (size_t)b*HW))[p4] = o;
    __syncthreads();
    if (t < 32) atomicAdd(&g_hist[b*32 + t], sh[t]);
}

// ---------------- Otsu + scalar params ----------------
__global__ void k_otsu_params(const float* __restrict__ cal_a, const float* __restrict__ cal_b,
                              const float* __restrict__ alpha_logits, const float* __restrict__ tau_p){
    int b = blockIdx.x;
    if (threadIdx.x != 0) return;
    float omega[32], mu[32];
    float denom = (float)HW + 1e-6f;
    float o = 0.0f, m = 0.0f;
    for (int k = 0; k < 32; k++){
        float pk = (float)g_hist[b*32 + k] / denom;
        float xk = (float)k / 31.0f;
        o += pk; m += pk*xk;
        omega[k] = o; mu[k] = m;
    }
    float mu_t = mu[31];
    float best = -1e30f; int kb = 0;
    for (int k = 0; k < 32; k++){
        float num = mu_t*omega[k] - mu[k];
        float s   = num*num / (omega[k]*(1.0f - omega[k]) + 1e-8f);
        if (s > best){ best = s; kb = k; }
    }
    g_thr[b] = (float)kb / 32.0f;
    if (b == 0){
        float al[4]; float mx = -1e30f;
        for (int c = 0; c < 4; c++){ al[c] = alpha_logits[c]; mx = fmaxf(mx, al[c]); }
        float s = 0.0f;
        for (int c = 0; c < 4; c++){ al[c] = expf(al[c] - mx); s += al[c]; }
        for (int c = 0; c < 4; c++){
            g_par[c]     = softplusf(cal_a[c]);
            g_par[4 + c] = cal_b[c];
            g_par[8 + c] = al[c]/s;
        }
        g_par[12] = 0.2f + softplusf(tau_p[0]);
    }
}

// ---------------- bit-packed morphology: tiled, 512 blocks ----------------
__device__ __forceinline__ unsigned h_ero(const unsigned* S, int r, int k){
    unsigned w = S[r*WORDS_ROW + k];
    unsigned p = (k > 0)             ? S[r*WORDS_ROW + k - 1] : 0u;
    unsigned n = (k < WORDS_ROW - 1) ? S[r*WORDS_ROW + k + 1] : 0u;
    unsigned L = (w << 1) | ((k > 0)             ? (p >> 31) : 1u);
    unsigned R = (w >> 1) | ((k < WORDS_ROW - 1) ? (n << 31) : 0x80000000u);
    return L & w & R;
}
__device__ __forceinline__ unsigned h_dil(const unsigned* S, int r, int k){
    unsigned w = S[r*WORDS_ROW + k];
    unsigned p = (k > 0)             ? S[r*WORDS_ROW + k - 1] : 0u;
    unsigned n = (k < WORDS_ROW - 1) ? S[r*WORDS_ROW + k + 1] : 0u;
    unsigned L = (w << 1) | (p >> 31);
    unsigned R = (w >> 1) | (n << 31);
    return L | w | R;
}
__device__ __forceinline__ unsigned erode3T(const unsigned* S, int r, int k, int gy){
    unsigned v = h_ero(S, r, k);
    if (gy > 0     && r > 0)      v &= h_ero(S, r-1, k);
    if (gy < HH-1  && r < SR-1)   v &= h_ero(S, r+1, k);
    return v;
}
__device__ __forceinline__ unsigned dilate3T(const unsigned* S, int r, int k, int gy){
    unsigned v = h_dil(S, r, k);
    if (gy > 0     && r > 0)      v |= h_dil(S, r-1, k);
    if (gy < HH-1  && r < SR-1)   v |= h_dil(S, r+1, k);
    return v;
}

#define MORPH_STEP(FN)                                              \
    {                                                               \
        unsigned nv[3];                                             \
        _Pragma("unroll")                                           \
        for (int s = 0; s < 3; s++){                                \
            int idx = tid + s*MT;                                   \
            if (idx < SW){                                          \
                int r = idx >> 4, k = idx & 15;                     \
                nv[s] = FN(S, r, k, ty0 - HALO + r);                \
            }                                                       \
        }                                                           \
        __syncthreads();                                            \
        _Pragma("unroll")                                           \
        for (int s = 0; s < 3; s++){                                \
            int idx = tid + s*MT;                                   \
            if (idx < SW) S[idx] = nv[s];                           \
        }                                                           \
        __syncthreads();                                            \
    }

__global__ void __launch_bounds__(MT) k_morph(){
    __shared__ unsigned S[SW];
    int b   = blockIdx.y;
    int ty0 = blockIdx.x*TR;
    int tid = threadIdx.x;
    float thr = g_thr[b];
    const float* g = g_gray + (size_t)b*HW;

    // threshold -> bits (float4 loads)
    #pragma unroll
    for (int s = 0; s < 3; s++){
        int idx = tid + s*MT;
        if (idx < SW){
            int r = idx >> 4, k = idx & 15;
            int gy = ty0 - HALO + r;
            unsigned w = 0;
            if (gy >= 0 && gy < HH){
                const float4* row = (const float4*)(g + gy*WW + k*32);
                #pragma unroll
                for (int j = 0; j < 8; j++){
                    float4 v4 = row[j];
                    w |= (v4.x <= thr ? 1u : 0u) << (4*j);
                    w |= (v4.y <= thr ? 1u : 0u) << (4*j+1);
                    w |= (v4.z <= thr ? 1u : 0u) << (4*j+2);
                    w |= (v4.w <= thr ? 1u : 0u) << (4*j+3);
                }
            }
            S[idx] = w;
        }
    }
    __syncthreads();

    MORPH_STEP(erode3T)
    MORPH_STEP(dilate3T)
    MORPH_STEP(dilate3T)
    MORPH_STEP(erode3T)    // S = nuc

    // nuc + bnd output for center rows (TR*16 = 256 words, 1/thread)
    {
        int idx = tid;
        int r = (idx >> 4) + HALO, k = idx & 15;
        int gy = ty0 - HALO + r;
        unsigned nu = S[r*WORDS_ROW + k];
        unsigned er = erode3T(S, r, k, gy);
        g_nucbits[b*WORDS_IMG + gy*WORDS_ROW + k] = nu;
        g_bndbits[b*WORDS_IMG + gy*WORDS_ROW + k] = nu & ~er;
    }
    // rowmax11
    {
        unsigned nv[3];
        #pragma unroll
        for (int s = 0; s < 3; s++){
            int idx = tid + s*MT;
            if (idx < SW){
                int r = idx >> 4, k = idx & 15;
                unsigned w = S[r*WORDS_ROW + k];
                unsigned p = (k > 0)             ? S[r*WORDS_ROW + k - 1] : 0u;
                unsigned n = (k < WORDS_ROW - 1) ? S[r*WORDS_ROW + k + 1] : 0u;
                unsigned long long lo = ((unsigned long long)w << 32) | p;
                unsigned long long hi = ((unsigned long long)n << 32) | w;
                unsigned v = w;
                #pragma unroll
                for (int sh = 1; sh <= 5; sh++){
                    v |= (unsigned)(lo >> (32 - sh));
                    v |= (unsigned)(hi >> sh);
                }
                nv[s] = v;
            }
        }
        __syncthreads();
        #pragma unroll
        for (int s = 0; s < 3; s++){
            int idx = tid + s*MT;
            if (idx < SW) S[idx] = nv[s];
        }
        __syncthreads();
    }
    // colmax11 -> cell bits for center rows
    {
        int idx = tid;
        int r = (idx >> 4) + HALO, k = idx & 15;
        int gy = ty0 - HALO + r;
        int d0 = (gy - 5 < 0)    ? -gy          : -5;
        int d1 = (gy + 5 > HH-1) ? (HH-1 - gy)  :  5;
        unsigned v = 0;
        for (int d = d0; d <= d1; d++) v |= S[(r + d)*WORDS_ROW + k];
        g_cellbits[b*WORDS_IMG + gy*WORDS_ROW + k] = v;
    }
}

// ---------------- fused maps kernel ----------------
__device__ __forceinline__ unsigned winN(const unsigned* w3, int rel, int width){
    unsigned long long c = ((unsigned long long)w3[1] << 32) | (unsigned long long)w3[0];
    unsigned long long v = c >> rel;
    if (rel + width > 64) v |= ((unsigned long long)w3[2]) << (64 - rel);
    return (unsigned)v & ((1u << width) - 1u);
}
__device__ __forceinline__ unsigned bit1(const unsigned* w3, int pos){
    return (w3[pos >> 5] >> (pos & 31)) & 1u;
}

__global__ void __launch_bounds__(1024) k_fused(float* __restrict__ out){
    __shared__ float sg[42*43];
    __shared__ float ssn[40*40];
    __shared__ float scs[40*40];
    __shared__ float vs0[32*40], vs1[32*40], vs2[32*40], vs3[32*40];
    __shared__ unsigned nucw[40*3], cellw[40*3], bndw[40*3];
    __shared__ float wred[32];

    int tx = threadIdx.x, ty = threadIdx.y;
    int tid = ty*32 + tx;
    int tx0 = blockIdx.x*32, ty0 = blockIdx.y*32;
    int b = blockIdx.z;
    const float* g = g_gray + (size_t)b*HW;

    for (int idx = tid; idx < 42*42; idx += 1024){
        int rr = idx/42, cc = idx%42;
        int gy = ty0 - 5 + rr, gx = tx0 - 5 + cc;
        float v = 0.0f;
        if (gy >= 0 && gy < HH && gx >= 0 && gx < WW) v = g[gy*WW + gx];
        sg[rr*43 + cc] = v;
    }
    {
        int kw0 = (tx0 >> 5) - 1;
        for (int idx = tid; idx < 120; idx += 1024){
            int r = idx/3, c = idx%3;
            int gy = ty0 - 4 + r;
            int kw = kw0 + c;
            unsigned nv = 0, cv = 0, bv = 0;
            if (gy >= 0 && gy < HH && kw >= 0 && kw < WORDS_ROW){
                int off = b*WORDS_IMG + gy*WORDS_ROW + kw;
                nv = g_nucbits[off]; cv = g_cellbits[off]; bv = g_bndbits[off];
            }
            nucw[idx] = nv; cellw[idx] = cv; bndw[idx] = bv;
        }
    }
    __syncthreads();

    for (int idx = tid; idx < 40*40; idx += 1024){
        int r = idx/40, c = idx%40;
        int gy = ty0 - 4 + r, gx = tx0 - 4 + c;
        float sn = 0.0f, cs = 0.0f;
        if (gy >= 0 && gy < HH && gx >= 0 && gx < WW){
            const float* p = sg + r*43 + c;
            float v00 = p[0],  v01 = p[1],  v02 = p[2];
            float v10 = p[43],              v12 = p[45];
            float v20 = p[86], v21 = p[87], v22 = p[88];
            float gxv = (v00 + 2.0f*v10 + v20) - (v02 + 2.0f*v12 + v22);
            float gyv = (v00 + 2.0f*v01 + v02) - (v20 + 2.0f*v21 + v22);
            float r2 = gxv*gxv + gyv*gyv;
            if (r2 > 0.0f){
                float rr = sqrtf(r2);
                sn = gyv/rr; cs = gxv/rr;
            } else { sn = 0.0f; cs = 1.0f; }
        }
        ssn[idx] = sn; scs[idx] = cs;
    }
    __syncthreads();

    for (int idx = tid; idx < 32*40; idx += 1024){
        int yi = idx/40, j = idx%40;
        float a = 0.0f, bq = 0.0f, cq = 0.0f, dq = 0.0f;
        #pragma unroll
        for (int k = 0; k < 9; k++){
            a  += ssn[(yi+k)*40 + j];
            bq += scs[(yi+k)*40 + j];
            float gv = sg[(yi+1+k)*43 + (j+1)];
            cq += gv;
            dq += gv*gv;
        }
        vs0[idx] = a; vs1[idx] = bq; vs2[idx] = cq; vs3[idx] = dq;
    }
    __syncthreads();

    int xi = tx, yi = ty;
    int gx = tx0 + xi, gy = ty0 + yi;
    float s_sn = 0.0f, s_cs = 0.0f, s_g = 0.0f, s_g2 = 0.0f;
    #pragma unroll
    for (int k = 0; k < 9; k++){
        int j = yi*40 + xi + k;
        s_sn += vs0[j]; s_cs += vs1[j]; s_g += vs2[j]; s_g2 += vs3[j];
    }
    int rows_in = (gy+4 > HH-1 ? HH-1 : gy+4) - (gy-4 < 0 ? 0 : gy-4) + 1;
    int cols_in = (gx+4 > WW-1 ? WW-1 : gx+4) - (gx-4 < 0 ? 0 : gx-4) + 1;
    float den = (float)(rows_in*cols_in) + 1e-6f;

    float ms = s_sn/den, mc = s_cs/den;
    float circ = 1.0f - sqrtf(ms*ms + mc*mc + 1e-6f);
    float g1 = s_g/den, g2v = s_g2/den;
    float ent = log1pf(fmaxf(g2v - g1*g1, 0.0f));

    int an = 0, csum = 0;
    #pragma unroll
    for (int k = 0; k < 9; k++){
        an   += __popc(winN(&nucw[(yi+k)*3],  xi + 28, 9));
        csum += __popc(winN(&cellw[(yi+k)*3], xi + 28, 9));
    }
    float A_n = (float)an;
    float A_c = fmaxf((float)(csum - an), 1.0f);
    float ncv = A_n / A_c;

    unsigned cbit = bit1(&nucw[(yi+4)*3], xi + 32);
    unsigned up   = bit1(&nucw[(yi+3)*3], xi + 32);
    unsigned dn   = bit1(&nucw[(yi+5)*3], xi + 32);
    unsigned lf   = bit1(&nucw[(yi+4)*3], xi + 31);
    unsigned rt   = bit1(&nucw[(yi+4)*3], xi + 33);
    float lap = fabsf((float)(up + dn + lf + rt) - 4.0f*(float)cbit);
    unsigned bc = bit1(&bndw[(yi+4)*3], xi + 32);
    int bs = 0;
    #pragma unroll
    for (int k = 0; k < 5; k++)
        bs += __popc(winN(&bndw[(yi+2+k)*3], xi + 30, 5));
    float rough = lap*(float)bc / ((float)bs + 1e-6f);

    size_t pix = (size_t)gy*WW + gx;
    float* z = out + (size_t)NPIX + (size_t)b*4*HW + pix;
    __stcs(z,        rough);
    __stcs(z + HW,   circ);
    __stcs(z + 2*HW, ncv);
    __stcs(z + 3*HW, ent);
    __stcs(out + 5*(size_t)NPIX + (size_t)b*HW + pix, (float)cbit);

    float z0s = log1pf(fmaxf(rough, 0.0f));
    float z1s = fminf(fmaxf(circ, 0.0f), 1.0f);
    float z2s = log1pf(fmaxf(ncv, 0.0f));
    float z3s = fminf(fmaxf(ent, 0.0f), 3.4657359f);
    float E = g_par[8 ]*(g_par[0]*z0s + g_par[4])
            + g_par[9 ]*(g_par[1]*z1s + g_par[5])
            + g_par[10]*(g_par[2]*z2s + g_par[6])
            + g_par[11]*(g_par[3]*z3s + g_par[7]);
    // normal store: E is re-read by k_A; keep it L2-resident
    out[6*(size_t)NPIX + (size_t)b*HW + pix] = E;

    // softmax partials via warp shuffles (2 barriers instead of ~20)
    float invtau = 1.0f / g_par[12];
    float zz = -E*invtau;
    float m = zz;
    #pragma unroll
    for (int o = 16; o > 0; o >>= 1) m = fmaxf(m, __shfl_xor_sync(0xFFFFFFFFu, m, o));
    if (tx == 0) wred[ty] = m;
    __syncthreads();
    if (ty == 0){
        float mm = wred[tx];
        #pragma unroll
        for (int o = 16; o > 0; o >>= 1) mm = fmaxf(mm, __shfl_xor_sync(0xFFFFFFFFu, mm, o));
        if (tx == 0) wred[0] = mm;
    }
    __syncthreads();
    float M = wred[0];
    float e = expf(zz - M);
    #pragma unroll
    for (int o = 16; o > 0; o >>= 1) e += __shfl_xor_sync(0xFFFFFFFFu, e, o);
    __syncthreads();           // wred[1..31] free for reuse
    if (tx == 0) wred[ty] = e;
    __syncthreads();
    if (ty == 0){
        float ss = wred[tx];
        #pragma unroll
        for (int o = 16; o > 0; o >>= 1) ss += __shfl_xor_sync(0xFFFFFFFFu, ss, o);
        if (tx == 0){
            int tile = blockIdx.y*16 + blockIdx.x;
            g_part[(b*256 + tile)*2    ] = M;
            g_part[(b*256 + tile)*2 + 1] = ss;
        }
    }
}

// ---------------- combine softmax partials ----------------
__global__ void k_combine(){
    __shared__ float sm[256], ss[256];
    int b = blockIdx.x, t = threadIdx.x;
    float m = g_part[(b*256 + t)*2];
    float s = g_part[(b*256 + t)*2 + 1];
    sm[t] = m;
    __syncthreads();
    for (int st = 128; st > 0; st >>= 1){
        if (t < st) sm[t] = fmaxf(sm[t], sm[t + st]);
        __syncthreads();
    }
    float M = sm[0];
    __syncthreads();
    ss[t] = s*expf(m - M);
    __syncthreads();
    for (int st = 128; st > 0; st >>= 1){
        if (t < st) ss[t] += ss[t + st];
        __syncthreads();
    }
    if (t == 0){ g_red[b*2] = M; g_red[b*2 + 1] = ss[0]; }
}

// ---------------- final A (float4) ----------------
__global__ void k_A(float* __restrict__ out){
    int b = blockIdx.y;
    int p4 = blockIdx.x*blockDim.x + threadIdx.x;
    float invtau = 1.0f / g_par[12];
    float M = g_red[b*2];
    float S = g_red[b*2 + 1];
    float4 E4 = ((const float4*)(out + 6*(size_t)NPIX + (size_t)b*HW))[p4];
    float4 A4;
    A4.x = expf(-E4.x*invtau - M) / S;
    A4.y = expf(-E4.y*invtau - M) / S;
    A4.z = expf(-E4.z*invtau - M) / S;
    A4.w = expf(-E4.w*invtau - M) / S;
    __stcs((float4*)(out + (size_t)b*HW) + p4, A4);
}

// ---------------- launch ----------------
extern "C" void kernel_launch(void* const* d_in, const int* in_sizes, int n_in,
                              void* d_out, int out_size){
    const float* img    = (const float*)d_in[0];
    const float* cal_a  = (const float*)d_in[1];
    const float* cal_b  = (const float*)d_in[2];
    const float* alpha  = (const float*)d_in[3];
    const float* tau_p  = (const float*)d_in[4];
    float* out = (float*)d_out;
    (void)in_sizes; (void)n_in; (void)out_size;

    k_zero_hist<<<2, 256>>>();
    k_gray_hist<<<dim3(HW/(256*4), BB, 1), 256>>>(img);
    k_otsu_params<<<BB, 32>>>(cal_a, cal_b, alpha, tau_p);
    k_morph<<<dim3(HH/TR, BB, 1), MT>>>();
    k_fused<<<dim3(16, 16, BB), dim3(32, 32, 1)>>>(out);
    k_combine<<<BB, 256>>>();
    k_A<<<dim3(HW/(256*4), BB, 1), 256>>>(out);
}

// round 6
// speedup vs baseline: 2.1448x; 1.1001x over previous
#include <cuda_runtime.h>
#include <math.h>

#define BB 16
#define HH 512
#define WW 512
#define HW (HH*WW)
#define NPIX (BB*HW)
#define WORDS_ROW 16           // 512/32
#define WORDS_IMG (HH*WORDS_ROW)

// morph tiling
#define TR 16
#define HALO 9
#define SR (TR + 2*HALO)       // 34 rows
#define SW (SR*WORDS_ROW)      // 544 words
#define MT 256

// ---------------- scratch (device globals: alloc-free rule) ----------------
static __device__ float    g_gray[NPIX];
static __device__ int      g_hist[BB*32];
static __device__ float    g_thr[BB];
static __device__ unsigned g_nucbits[BB*WORDS_IMG];
static __device__ unsigned g_cellbits[BB*WORDS_IMG];
static __device__ unsigned g_bndbits[BB*WORDS_IMG];
static __device__ float    g_par[13];
static __device__ float    g_part[BB*256*2];
static __device__ float    g_red[BB*2];

__device__ __forceinline__ float softplusf(float v){
    return fmaxf(v, 0.0f) + log1pf(expf(-fabsf(v)));
}

// ---------------- gray + histogram (float4: 4 px/thread) ----------------
__global__ void k_zero_hist(){
    int i = blockIdx.x*blockDim.x + threadIdx.x;
    if (i < BB*32) g_hist[i] = 0;
}

__global__ void k_gray_hist(const float* __restrict__ img){
    __shared__ int sh[32];
    int t = threadIdx.x;
    if (t < 32) sh[t] = 0;
    __syncthreads();
    int b = blockIdx.y;
    int p4 = blockIdx.x*blockDim.x + t;
    const float4* imr = (const float4*)(img + (size_t)b*3*HW);
    const float4* img_ = imr + (HW/4);
    const float4* imb = imr + 2*(HW/4);
    float4 r4 = __ldcs(imr + p4);
    float4 g4 = __ldcs(img_ + p4);
    float4 b4 = __ldcs(imb + p4);
    float gr[4];
    gr[0] = 0.5f*(0.299f*r4.x + 0.587f*g4.x + 0.114f*b4.x + 1.0f);
    gr[1] = 0.5f*(0.299f*r4.y + 0.587f*g4.y + 0.114f*b4.y + 1.0f);
    gr[2] = 0.5f*(0.299f*r4.z + 0.587f*g4.z + 0.114f*b4.z + 1.0f);
    gr[3] = 0.5f*(0.299f*r4.w + 0.587f*g4.w + 0.114f*b4.w + 1.0f);
    float4 o;
    #pragma unroll
    for (int j = 0; j < 4; j++){
        gr[j] = fminf(fmaxf(gr[j], 0.0f), 1.0f);
        int idx = (int)(gr[j]*32.0f);
        idx = idx < 0 ? 0 : (idx > 31 ? 31 : idx);
        atomicAdd(&sh[idx], 1);
    }
    o.x = gr[0]; o.y = gr[1]; o.z = gr[2]; o.w = gr[3];
    ((float4*)(g_gray + (size_t)b*HW))[p4] = o;
    __syncthreads();
    if (t < 32) atomicAdd(&g_hist[b*32 + t], sh[t]);
}

// ---------------- Otsu + scalar params ----------------
__global__ void k_otsu_params(const float* __restrict__ cal_a, const float* __restrict__ cal_b,
                              const float* __restrict__ alpha_logits, const float* __restrict__ tau_p){
    int b = blockIdx.x;
    if (threadIdx.x != 0) return;
    float omega[32], mu[32];
    float denom = (float)HW + 1e-6f;
    float o = 0.0f, m = 0.0f;
    for (int k = 0; k < 32; k++){
        float pk = (float)g_hist[b*32 + k] / denom;
        float xk = (float)k / 31.0f;
        o += pk; m += pk*xk;
        omega[k] = o; mu[k] = m;
    }
    float mu_t = mu[31];
    float best = -1e30f; int kb = 0;
    for (int k = 0; k < 32; k++){
        float num = mu_t*omega[k] - mu[k];
        float s   = num*num / (omega[k]*(1.0f - omega[k]) + 1e-8f);
        if (s > best){ best = s; kb = k; }
    }
    g_thr[b] = (float)kb / 32.0f;
    if (b == 0){
        float al[4]; float mx = -1e30f;
        for (int c = 0; c < 4; c++){ al[c] = alpha_logits[c]; mx = fmaxf(mx, al[c]); }
        float s = 0.0f;
        for (int c = 0; c < 4; c++){ al[c] = expf(al[c] - mx); s += al[c]; }
        for (int c = 0; c < 4; c++){
            g_par[c]     = softplusf(cal_a[c]);
            g_par[4 + c] = cal_b[c];
            g_par[8 + c] = al[c]/s;
        }
        g_par[12] = 0.2f + softplusf(tau_p[0]);
    }
}

// ---------------- bit-packed morphology ----------------
__device__ __forceinline__ unsigned h_ero(const unsigned* S, int r, int k){
    unsigned w = S[r*WORDS_ROW + k];
    unsigned p = (k > 0)             ? S[r*WORDS_ROW + k - 1] : 0u;
    unsigned n = (k < WORDS_ROW - 1) ? S[r*WORDS_ROW + k + 1] : 0u;
    unsigned L = (w << 1) | ((k > 0)             ? (p >> 31) : 1u);
    unsigned R = (w >> 1) | ((k < WORDS_ROW - 1) ? (n << 31) : 0x80000000u);
    return L & w & R;
}
__device__ __forceinline__ unsigned h_dil(const unsigned* S, int r, int k){
    unsigned w = S[r*WORDS_ROW + k];
    unsigned p = (k > 0)             ? S[r*WORDS_ROW + k - 1] : 0u;
    unsigned n = (k < WORDS_ROW - 1) ? S[r*WORDS_ROW + k + 1] : 0u;
    unsigned L = (w << 1) | (p >> 31);
    unsigned R = (w >> 1) | (n << 31);
    return L | w | R;
}
__device__ __forceinline__ unsigned erode3T(const unsigned* S, int r, int k, int gy){
    unsigned v = h_ero(S, r, k);
    if (gy > 0     && r > 0)      v &= h_ero(S, r-1, k);
    if (gy < HH-1  && r < SR-1)   v &= h_ero(S, r+1, k);
    return v;
}
__device__ __forceinline__ unsigned dilate3T(const unsigned* S, int r, int k, int gy){
    unsigned v = h_dil(S, r, k);
    if (gy > 0     && r > 0)      v |= h_dil(S, r-1, k);
    if (gy < HH-1  && r < SR-1)   v |= h_dil(S, r+1, k);
    return v;
}

#define MORPH_STEP(FN)                                              \
    {                                                               \
        unsigned nv[3];                                             \
        _Pragma("unroll")                                           \
        for (int s = 0; s < 3; s++){                                \
            int idx = tid + s*MT;                                   \
            if (idx < SW){                                          \
                int r = idx >> 4, k = idx & 15;                     \
                nv[s] = FN(S, r, k, ty0 - HALO + r);                \
            }                                                       \
        }                                                           \
        __syncthreads();                                            \
        _Pragma("unroll")                                           \
        for (int s = 0; s < 3; s++){                                \
            int idx = tid + s*MT;                                   \
            if (idx < SW) S[idx] = nv[s];                           \
        }                                                           \
        __syncthreads();                                            \
    }

__global__ void __launch_bounds__(MT) k_morph(){
    __shared__ unsigned S[SW];
    int b   = blockIdx.y;
    int ty0 = blockIdx.x*TR;
    int tid = threadIdx.x;
    float thr = g_thr[b];
    const float* g = g_gray + (size_t)b*HW;

    #pragma unroll
    for (int s = 0; s < 3; s++){
        int idx = tid + s*MT;
        if (idx < SW){
            int r = idx >> 4, k = idx & 15;
            int gy = ty0 - HALO + r;
            unsigned w = 0;
            if (gy >= 0 && gy < HH){
                const float4* row = (const float4*)(g + gy*WW + k*32);
                #pragma unroll
                for (int j = 0; j < 8; j++){
                    float4 v4 = row[j];
                    w |= (v4.x <= thr ? 1u : 0u) << (4*j);
                    w |= (v4.y <= thr ? 1u : 0u) << (4*j+1);
                    w |= (v4.z <= thr ? 1u : 0u) << (4*j+2);
                    w |= (v4.w <= thr ? 1u : 0u) << (4*j+3);
                }
            }
            S[idx] = w;
        }
    }
    __syncthreads();

    MORPH_STEP(erode3T)
    MORPH_STEP(dilate3T)
    MORPH_STEP(dilate3T)
    MORPH_STEP(erode3T)

    {
        int idx = tid;
        int r = (idx >> 4) + HALO, k = idx & 15;
        int gy = ty0 - HALO + r;
        unsigned nu = S[r*WORDS_ROW + k];
        unsigned er = erode3T(S, r, k, gy);
        g_nucbits[b*WORDS_IMG + gy*WORDS_ROW + k] = nu;
        g_bndbits[b*WORDS_IMG + gy*WORDS_ROW + k] = nu & ~er;
    }
    {
        unsigned nv[3];
        #pragma unroll
        for (int s = 0; s < 3; s++){
            int idx = tid + s*MT;
            if (idx < SW){
                int r = idx >> 4, k = idx & 15;
                unsigned w = S[r*WORDS_ROW + k];
                unsigned p = (k > 0)             ? S[r*WORDS_ROW + k - 1] : 0u;
                unsigned n = (k < WORDS_ROW - 1) ? S[r*WORDS_ROW + k + 1] : 0u;
                unsigned long long lo = ((unsigned long long)w << 32) | p;
                unsigned long long hi = ((unsigned long long)n << 32) | w;
                unsigned v = w;
                #pragma unroll
                for (int sh = 1; sh <= 5; sh++){
                    v |= (unsigned)(lo >> (32 - sh));
                    v |= (unsigned)(hi >> sh);
                }
                nv[s] = v;
            }
        }
        __syncthreads();
        #pragma unroll
        for (int s = 0; s < 3; s++){
            int idx = tid + s*MT;
            if (idx < SW) S[idx] = nv[s];
        }
        __syncthreads();
    }
    {
        int idx = tid;
        int r = (idx >> 4) + HALO, k = idx & 15;
        int gy = ty0 - HALO + r;
        int d0 = (gy - 5 < 0)    ? -gy          : -5;
        int d1 = (gy + 5 > HH-1) ? (HH-1 - gy)  :  5;
        unsigned v = 0;
        for (int d = d0; d <= d1; d++) v |= S[(r + d)*WORDS_ROW + k];
        g_cellbits[b*WORDS_IMG + gy*WORDS_ROW + k] = v;
    }
}

// ---------------- fused maps kernel ----------------
__device__ __forceinline__ unsigned winN(const unsigned* w3, int rel, int width){
    unsigned long long c = ((unsigned long long)w3[1] << 32) | (unsigned long long)w3[0];
    unsigned long long v = c >> rel;
    if (rel + width > 64) v |= ((unsigned long long)w3[2]) << (64 - rel);
    return (unsigned)v & ((1u << width) - 1u);
}
__device__ __forceinline__ unsigned bit1(const unsigned* w3, int pos){
    return (w3[pos >> 5] >> (pos & 31)) & 1u;
}

__global__ void __launch_bounds__(1024, 2) k_fused(float* __restrict__ out){
    __shared__ float sg[42*43];
    __shared__ float p0[40*40];               // sin, later vsum(gray)
    __shared__ float p1[40*40];               // cos, later vsum(gray^2)
    __shared__ float vs0[32*40], vs1[32*40];  // vsum(sin), vsum(cos)
    __shared__ unsigned nucw[40*3], cellw[40*3], bndw[40*3];
    __shared__ float wred[32];

    int tx = threadIdx.x, ty = threadIdx.y;
    int tid = ty*32 + tx;
    int tx0 = blockIdx.x*32, ty0 = blockIdx.y*32;
    int b = blockIdx.z;
    const float* g = g_gray + (size_t)b*HW;

    for (int idx = tid; idx < 42*42; idx += 1024){
        int rr = idx/42, cc = idx%42;
        int gy = ty0 - 5 + rr, gx = tx0 - 5 + cc;
        float v = 0.0f;
        if (gy >= 0 && gy < HH && gx >= 0 && gx < WW) v = g[gy*WW + gx];
        sg[rr*43 + cc] = v;
    }
    {
        int kw0 = (tx0 >> 5) - 1;
        for (int idx = tid; idx < 120; idx += 1024){
            int r = idx/3, c = idx%3;
            int gy = ty0 - 4 + r;
            int kw = kw0 + c;
            unsigned nv = 0, cv = 0, bv = 0;
            if (gy >= 0 && gy < HH && kw >= 0 && kw < WORDS_ROW){
                int off = b*WORDS_IMG + gy*WORDS_ROW + kw;
                nv = g_nucbits[off]; cv = g_cellbits[off]; bv = g_bndbits[off];
            }
            nucw[idx] = nv; cellw[idx] = cv; bndw[idx] = bv;
        }
    }
    __syncthreads();

    // stage1: sobel -> unit vector (rsqrt; no divides)
    for (int idx = tid; idx < 40*40; idx += 1024){
        int r = idx/40, c = idx%40;
        int gy = ty0 - 4 + r, gx = tx0 - 4 + c;
        float sn = 0.0f, cs = 0.0f;
        if (gy >= 0 && gy < HH && gx >= 0 && gx < WW){
            const float* p = sg + r*43 + c;
            float v00 = p[0],  v01 = p[1],  v02 = p[2];
            float v10 = p[43],              v12 = p[45];
            float v20 = p[86], v21 = p[87], v22 = p[88];
            float gxv = (v00 + 2.0f*v10 + v20) - (v02 + 2.0f*v12 + v22);
            float gyv = (v00 + 2.0f*v01 + v02) - (v20 + 2.0f*v21 + v22);
            float r2 = gxv*gxv + gyv*gyv;
            if (r2 > 0.0f){
                float inv = rsqrtf(r2);
                sn = gyv*inv; cs = gxv*inv;
            } else { sn = 0.0f; cs = 1.0f; }
        }
        p0[idx] = sn; p1[idx] = cs;
    }
    __syncthreads();

    // stage2a: vertical 9-sums of sin/cos
    for (int idx = tid; idx < 32*40; idx += 1024){
        int yi = idx/40, j = idx%40;
        float a = 0.0f, bq = 0.0f;
        #pragma unroll
        for (int k = 0; k < 9; k++){
            a  += p0[(yi+k)*40 + j];
            bq += p1[(yi+k)*40 + j];
        }
        vs0[idx] = a; vs1[idx] = bq;
    }
    __syncthreads();                 // p0/p1 fully read; safe to overwrite

    // stage2b: vertical 9-sums of gray/gray^2 into reused p0/p1
    for (int idx = tid; idx < 32*40; idx += 1024){
        int yi = idx/40, j = idx%40;
        float cq = 0.0f, dq = 0.0f;
        #pragma unroll
        for (int k = 0; k < 9; k++){
            float gv = sg[(yi+1+k)*43 + (j+1)];
            cq += gv;
            dq += gv*gv;
        }
        p0[idx] = cq; p1[idx] = dq;
    }
    __syncthreads();

    // stage3
    int xi = tx, yi = ty;
    int gx = tx0 + xi, gy = ty0 + yi;
    float s_sn = 0.0f, s_cs = 0.0f, s_g = 0.0f, s_g2 = 0.0f;
    #pragma unroll
    for (int k = 0; k < 9; k++){
        int j = yi*40 + xi + k;
        s_sn += vs0[j]; s_cs += vs1[j]; s_g += p0[j]; s_g2 += p1[j];
    }
    int rows_in = (gy+4 > HH-1 ? HH-1 : gy+4) - (gy-4 < 0 ? 0 : gy-4) + 1;
    int cols_in = (gx+4 > WW-1 ? WW-1 : gx+4) - (gx-4 < 0 ? 0 : gx-4) + 1;
    float den = (float)(rows_in*cols_in) + 1e-6f;
    float invden = __fdividef(1.0f, den);

    float ms = s_sn*invden, mc = s_cs*invden;
    float circ = 1.0f - sqrtf(ms*ms + mc*mc + 1e-6f);
    float g1 = s_g*invden, g2v = s_g2*invden;
    float ent = log1pf(fmaxf(g2v - g1*g1, 0.0f));

    int an = 0, csum = 0;
    #pragma unroll
    for (int k = 0; k < 9; k++){
        an   += __popc(winN(&nucw[(yi+k)*3],  xi + 28, 9));
        csum += __popc(winN(&cellw[(yi+k)*3], xi + 28, 9));
    }
    float A_n = (float)an;
    float A_c = fmaxf((float)(csum - an), 1.0f);
    float ncv = __fdividef(A_n, A_c);

    unsigned cbit = bit1(&nucw[(yi+4)*3], xi + 32);
    unsigned up   = bit1(&nucw[(yi+3)*3], xi + 32);
    unsigned dn   = bit1(&nucw[(yi+5)*3], xi + 32);
    unsigned lf   = bit1(&nucw[(yi+4)*3], xi + 31);
    unsigned rt   = bit1(&nucw[(yi+4)*3], xi + 33);
    float lap = fabsf((float)(up + dn + lf + rt) - 4.0f*(float)cbit);
    unsigned bc = bit1(&bndw[(yi+4)*3], xi + 32);
    int bs = 0;
    #pragma unroll
    for (int k = 0; k < 5; k++)
        bs += __popc(winN(&bndw[(yi+2+k)*3], xi + 30, 5));
    float rough = lap*(float)bc*__fdividef(1.0f, (float)bs + 1e-6f);

    size_t pix = (size_t)gy*WW + gx;
    float* z = out + (size_t)NPIX + (size_t)b*4*HW + pix;
    __stcs(z,        rough);
    __stcs(z + HW,   circ);
    __stcs(z + 2*HW, ncv);
    __stcs(z + 3*HW, ent);
    __stcs(out + 5*(size_t)NPIX + (size_t)b*HW + pix, (float)cbit);

    float z0s = log1pf(fmaxf(rough, 0.0f));
    float z1s = fminf(fmaxf(circ, 0.0f), 1.0f);
    float z2s = log1pf(fmaxf(ncv, 0.0f));
    float z3s = fminf(fmaxf(ent, 0.0f), 3.4657359f);
    float E = g_par[8 ]*(g_par[0]*z0s + g_par[4])
            + g_par[9 ]*(g_par[1]*z1s + g_par[5])
            + g_par[10]*(g_par[2]*z2s + g_par[6])
            + g_par[11]*(g_par[3]*z3s + g_par[7]);
    out[6*(size_t)NPIX + (size_t)b*HW + pix] = E;   // re-read by k_A: keep L2-resident

    // softmax partials via warp shuffles
    float invtau = __fdividef(1.0f, g_par[12]);
    float zz = -E*invtau;
    float m = zz;
    #pragma unroll
    for (int o = 16; o > 0; o >>= 1) m = fmaxf(m, __shfl_xor_sync(0xFFFFFFFFu, m, o));
    if (tx == 0) wred[ty] = m;
    __syncthreads();
    if (ty == 0){
        float mm = wred[tx];
        #pragma unroll
        for (int o = 16; o > 0; o >>= 1) mm = fmaxf(mm, __shfl_xor_sync(0xFFFFFFFFu, mm, o));
        if (tx == 0) wred[0] = mm;
    }
    __syncthreads();
    float M = wred[0];
    float e = __expf(zz - M);
    #pragma unroll
    for (int o = 16; o > 0; o >>= 1) e += __shfl_xor_sync(0xFFFFFFFFu, e, o);
    __syncthreads();
    if (tx == 0) wred[ty] = e;
    __syncthreads();
    if (ty == 0){
        float ss = wred[tx];
        #pragma unroll
        for (int o = 16; o > 0; o >>= 1) ss += __shfl_xor_sync(0xFFFFFFFFu, ss, o);
        if (tx == 0){
            int tile = blockIdx.y*16 + blockIdx.x;
            g_part[(b*256 + tile)*2    ] = M;
            g_part[(b*256 + tile)*2 + 1] = ss;
        }
    }
}

// ---------------- combine softmax partials ----------------
__global__ void k_combine(){
    __shared__ float sm[256], ss[256];
    int b = blockIdx.x, t = threadIdx.x;
    float m = g_part[(b*256 + t)*2];
    float s = g_part[(b*256 + t)*2 + 1];
    sm[t] = m;
    __syncthreads();
    for (int st = 128; st > 0; st >>= 1){
        if (t < st) sm[t] = fmaxf(sm[t], sm[t + st]);
        __syncthreads();
    }
    float M = sm[0];
    __syncthreads();
    ss[t] = s*expf(m - M);
    __syncthreads();
    for (int st = 128; st > 0; st >>= 1){
        if (t < st) ss[t] += ss[t + st];
        __syncthreads();
    }
    if (t == 0){ g_red[b*2] = M; g_red[b*2 + 1] = ss[0]; }
}

// ---------------- final A (float4) ----------------
__global__ void k_A(float* __restrict__ out){
    int b = blockIdx.y;
    int p4 = blockIdx.x*blockDim.x + threadIdx.x;
    float invtau = __fdividef(1.0f, g_par[12]);
    float M = g_red[b*2];
    float invS = __fdividef(1.0f, g_red[b*2 + 1]);
    float4 E4 = ((const float4*)(out + 6*(size_t)NPIX + (size_t)b*HW))[p4];
    float4 A4;
    A4.x = __expf(-E4.x*invtau - M)*invS;
    A4.y = __expf(-E4.y*invtau - M)*invS;
    A4.z = __expf(-E4.z*invtau - M)*invS;
    A4.w = __expf(-E4.w*invtau - M)*invS;
    __stcs((float4*)(out + (size_t)b*HW) + p4, A4);
}

// ---------------- launch ----------------
extern "C" void kernel_launch(void* const* d_in, const int* in_sizes, int n_in,
                              void* d_out, int out_size){
    const float* img    = (const float*)d_in[0];
    const float* cal_a  = (const float*)d_in[1];
    const float* cal_b  = (const float*)d_in[2];
    const float* alpha  = (const float*)d_in[3];
    const float* tau_p  = (const float*)d_in[4];
    float* out = (float*)d_out;
    (void)in_sizes; (void)n_in; (void)out_size;

    k_zero_hist<<<2, 256>>>();
    k_gray_hist<<<dim3(HW/(256*4), BB, 1), 256>>>(img);
    k_otsu_params<<<BB, 32>>>(cal_a, cal_b, alpha, tau_p);
    k_morph<<<dim3(HH/TR, BB, 1), MT>>>();
    k_fused<<<dim3(16, 16, BB), dim3(32, 32, 1)>>>(out);
    k_combine<<<BB, 256>>>();
    k_A<<<dim3(HW/(256*4), BB, 1), 256>>>(out);
}